// round 5
// baseline (speedup 1.0000x reference)
#include <cuda_runtime.h>
#include <cuda_bf16.h>
#include <cstdint>

// MissHitScatter: inputs [N=65536, D=1024] f32 -> out [P=4, N, D] f32.
// slice 0 = copy of input, slices 1..3 = zeros. 1.25 GiB total traffic.
//
// R4: uniform-work blocks. Every thread handles index i in slice 0:
//   load in[i]; store out[i] = in[i]; out[i+n4]=out[i+2n4]=out[i+3n4]=0.
// All blocks have identical read/write mix -> reads are spread across the
// whole kernel duration (no zero-only phases starving the read channels),
// and all waves are balanced. V=4 float4 per thread, loads batched (MLP=4),
// streaming stores for the write-once output.

#define V 4  // float4 per thread (in slice-0 index space)

__global__ void __launch_bounds__(256) misshit_scatter_kernel(
    const float4* __restrict__ in, float4* __restrict__ out, size_t n4)
{
    const float4 z = make_float4(0.f, 0.f, 0.f, 0.f);
    size_t base = (size_t)blockIdx.x * (blockDim.x * V) + threadIdx.x;

    if (base + (size_t)(V - 1) * blockDim.x < n4) {
        float4 v[V];
#pragma unroll
        for (int j = 0; j < V; j++)
            v[j] = __ldg(in + base + (size_t)j * blockDim.x);
#pragma unroll
        for (int j = 0; j < V; j++) {
            size_t i = base + (size_t)j * blockDim.x;
            __stwt(out + i, v[j]);
            __stwt(out + i + n4, z);
            __stwt(out + i + 2 * n4, z);
            __stwt(out + i + 3 * n4, z);
        }
    } else {
        // Tail guard (not taken for the benchmark shape: n4 % (256*V) == 0)
#pragma unroll
        for (int j = 0; j < V; j++) {
            size_t i = base + (size_t)j * blockDim.x;
            if (i < n4) {
                float4 v = __ldg(in + i);
                __stwt(out + i, v);
                __stwt(out + i + n4, z);
                __stwt(out + i + 2 * n4, z);
                __stwt(out + i + 3 * n4, z);
            }
        }
    }
}

extern "C" void kernel_launch(void* const* d_in, const int* in_sizes, int n_in,
                              void* d_out, int out_size) {
    const size_t n_elems = (size_t)in_sizes[0];   // 65536 * 1024 floats
    const size_t n4 = n_elems / 4;                // float4 per slice

    const int threads = 256;
    const size_t per_block = (size_t)threads * V;
    const int blocks = (int)((n4 + per_block - 1) / per_block);

    misshit_scatter_kernel<<<blocks, threads>>>(
        (const float4*)d_in[0], (float4*)d_out, n4);
}

// round 6
// speedup vs baseline: 1.0154x; 1.0154x over previous
#include <cuda_runtime.h>
#include <cuda_bf16.h>
#include <cstdint>

// MissHitScatter: inputs [N=65536, D=1024] f32 -> out [P=4, N, D] f32.
// slice 0 = input copy, slices 1..3 = zeros. 1.25 GiB traffic, one kernel.
//
// R5: R3's pure-contiguous blocks (copy chunk OR zero chunk, each a 32 KB
// contiguous span) but with the block->chunk mapping interleaved 1:3 so every
// wave has the same copy/zero mix: reads are spread evenly across the whole
// kernel duration without breaking per-warp store contiguity (R4's mistake).

#define V 8  // float4 per thread; chunk = 256*V float4 = 32 KB

__global__ void __launch_bounds__(256) misshit_scatter_kernel(
    const float4* __restrict__ in, float4* __restrict__ out, size_t n4)
{
    const size_t chunk_f4 = (size_t)blockDim.x * V;   // float4 per chunk
    const unsigned b = blockIdx.x;
    const unsigned c = b >> 2;        // group index
    const unsigned r = b & 3;         // 0 => copy chunk, 1..3 => zero chunk
    const size_t n_copy_chunks = n4 / chunk_f4;       // 8192 for this shape

    if (r == 0) {
        // Copy chunk c: contiguous span in slice 0.
        size_t base = (size_t)c * chunk_f4 + threadIdx.x;
        if (base + (size_t)(V - 1) * blockDim.x < n4) {
            float4 v[V];
#pragma unroll
            for (int j = 0; j < V; j++)
                v[j] = __ldg(in + base + (size_t)j * blockDim.x);
#pragma unroll
            for (int j = 0; j < V; j++)
                __stwt(out + base + (size_t)j * blockDim.x, v[j]);
        } else {
#pragma unroll
            for (int j = 0; j < V; j++) {
                size_t i = base + (size_t)j * blockDim.x;
                if (i < n4) __stwt(out + i, __ldg(in + i));
            }
        }
    } else {
        // Zero chunk k = c*3 + (r-1): contiguous span in slices 1..3.
        const float4 z = make_float4(0.f, 0.f, 0.f, 0.f);
        size_t k = (size_t)c * 3 + (r - 1);
        size_t base = n4 + k * chunk_f4 + threadIdx.x;
        size_t end = 4 * n4;
        if (base + (size_t)(V - 1) * blockDim.x < end) {
#pragma unroll
            for (int j = 0; j < V; j++)
                __stwt(out + base + (size_t)j * blockDim.x, z);
        } else {
#pragma unroll
            for (int j = 0; j < V; j++) {
                size_t i = base + (size_t)j * blockDim.x;
                if (i < end) __stwt(out + i, z);
            }
        }
    }
    (void)n_copy_chunks;
}

extern "C" void kernel_launch(void* const* d_in, const int* in_sizes, int n_in,
                              void* d_out, int out_size) {
    const size_t n_elems = (size_t)in_sizes[0];   // 65536 * 1024 floats
    const size_t n4 = n_elems / 4;                // 16Mi float4 per slice
    const size_t total4 = n4 * 4;                 // 64Mi float4 total

    const int threads = 256;
    const size_t per_block = (size_t)threads * V; // 2048 float4
    const int blocks = (int)((total4 + per_block - 1) / per_block);  // 32768

    misshit_scatter_kernel<<<blocks, threads>>>(
        (const float4*)d_in[0], (float4*)d_out, n4);
}